// round 5
// baseline (speedup 1.0000x reference)
#include <cuda_runtime.h>

// Problem constants (fixed by the dataset)
#define BB   256
#define NN   32
#define WW   1920
#define HH   1080
#define ROWS (BB * NN)   // 8192

// Scratch (alloc-free rule: __device__ globals)
__device__ float g_acc;
__device__ float g_count;
__device__ float g_mask[ROWS];

// ---------------------------------------------------------------------------
// Kernel 0: zero the accumulators (graph replays must be deterministic)
// ---------------------------------------------------------------------------
__global__ void hbdl_init_kernel() {
    g_acc = 0.0f;
    g_count = 0.0f;
}

// ---------------------------------------------------------------------------
// Kernel 1: per-row work — mask, valid count, target-gather terms.
//   loss_row = (-lp[t] - (sum_l1p - l1p[t])) / L
// Here we accumulate the (-lp[t] + l1p[t])/L part; kernel 2 handles -sum_l1p/L.
// ---------------------------------------------------------------------------
__global__ void hbdl_rows_kernel(const float* __restrict__ px,
                                 const float* __restrict__ py,
                                 const long long* __restrict__ tgt) {
    int r = blockIdx.x * blockDim.x + threadIdx.x;
    if (r >= ROWS) return;

    int tx = (int)tgt[2 * (size_t)r + 0];
    int ty = (int)tgt[2 * (size_t)r + 1];
    tx = min(max(tx, 0), WW - 1);
    ty = min(max(ty, 0), HH - 1);

    float m = ((tx == 0) && (ty == 0)) ? 0.0f : 1.0f;
    g_mask[r] = m;

    if (m != 0.0f) {
        float p = px[(size_t)r * WW + tx];
        float lp  = fmaxf(__logf(p),        -100.0f);
        float l1p = fmaxf(__logf(1.0f - p), -100.0f);
        float cx = (l1p - lp) * (1.0f / (float)WW);

        float q = py[(size_t)r * HH + ty];
        float lq  = fmaxf(__logf(q),        -100.0f);
        float l1q = fmaxf(__logf(1.0f - q), -100.0f);
        float cy = (l1q - lq) * (1.0f / (float)HH);

        atomicAdd(&g_acc, cx + cy);
        atomicAdd(&g_count, 1.0f);
    }
}

// ---------------------------------------------------------------------------
// Kernel 2: the big streaming reduction. One block per row.
//   blocks [0, ROWS)        -> pred_x row (1920 f32 = 480 float4)
//   blocks [ROWS, 2*ROWS)   -> pred_y row (1080 f32 = 270 float4)
// Accumulates  -mask * sum(log1p-clamped) / L  into g_acc.
// ---------------------------------------------------------------------------
__inline__ __device__ float warp_sum(float v) {
    #pragma unroll
    for (int o = 16; o > 0; o >>= 1)
        v += __shfl_xor_sync(0xffffffffu, v, o);
    return v;
}

__global__ void __launch_bounds__(256, 8)
hbdl_sum_kernel(const float* __restrict__ px, const float* __restrict__ py) {
    int bid = blockIdx.x;
    bool is_x = (bid < ROWS);
    int r = is_x ? bid : bid - ROWS;

    float m = g_mask[r];
    if (m == 0.0f) return;  // skip invalid rows entirely (no reads)

    const float4* ptr;
    int n4;
    float inv_l;
    if (is_x) {
        ptr = (const float4*)(px + (size_t)r * WW);
        n4 = WW / 4;                 // 480
        inv_l = 1.0f / (float)WW;
    } else {
        ptr = (const float4*)(py + (size_t)r * HH);
        n4 = HH / 4;                 // 270
        inv_l = 1.0f / (float)HH;
    }

    float s = 0.0f;
    for (int i = threadIdx.x; i < n4; i += blockDim.x) {
        float4 v = ptr[i];
        s += fmaxf(__logf(1.0f - v.x), -100.0f);
        s += fmaxf(__logf(1.0f - v.y), -100.0f);
        s += fmaxf(__logf(1.0f - v.z), -100.0f);
        s += fmaxf(__logf(1.0f - v.w), -100.0f);
    }

    // Block reduce: warp shuffles + shared
    __shared__ float sh[8];
    int lane = threadIdx.x & 31;
    int wid  = threadIdx.x >> 5;
    s = warp_sum(s);
    if (lane == 0) sh[wid] = s;
    __syncthreads();
    if (wid == 0) {
        float t = (lane < 8) ? sh[lane] : 0.0f;
        t = warp_sum(t);
        if (lane == 0)
            atomicAdd(&g_acc, -t * m * inv_l);
    }
}

// ---------------------------------------------------------------------------
// Kernel 3: finalize
// ---------------------------------------------------------------------------
__global__ void hbdl_final_kernel(float* __restrict__ out) {
    out[0] = g_acc / fmaxf(g_count, 1.0f);
}

// ---------------------------------------------------------------------------
// Launch contract
// ---------------------------------------------------------------------------
extern "C" void kernel_launch(void* const* d_in, const int* in_sizes, int n_in,
                              void* d_out, int out_size) {
    const float*     px  = (const float*)d_in[0];       // [256,32,1920] f32
    const float*     py  = (const float*)d_in[1];       // [256,32,1080] f32
    const long long* tgt = (const long long*)d_in[2];   // [256,32,2] i64
    float* out = (float*)d_out;

    hbdl_init_kernel<<<1, 1>>>();
    hbdl_rows_kernel<<<(ROWS + 255) / 256, 256>>>(px, py, tgt);
    hbdl_sum_kernel<<<2 * ROWS, 256>>>(px, py);
    hbdl_final_kernel<<<1, 1>>>(out);
}